// round 13
// baseline (speedup 1.0000x reference)
#include <cuda_runtime.h>
#include <cstdint>

// FeaturesLoss via mma.sync e4m3 m16n8k32, persistent CTAs.
// R13: = R12 (3 CTAs/SM, 128x64 tiles, BK=128) but MMA asm is NON-volatile so
// ptxas can interleave MMAs into LDSM latency shadows (tensor was 31% busy
// with strict volatile ordering freezing the per-warp LDSM->MMA timeline).

#define BM 128
#define BN 64
#define BK 128           // fp8 bytes per K-chunk = full row
#define NTHREADS 256
#define MAXN 4096
#define MAXD 512
#define SSTRB 144        // 128+16 bytes: odd 16B-granule stride, conflict-free
#define NSTG 2

#define STAGE_A_BYTES (BM * SSTRB)           // 18432
#define STAGE_B_BYTES (BN * SSTRB)           // 9216
#define SM_A 0
#define SM_B (NSTG * STAGE_A_BYTES)           // 36864
#define SM_SQA (SM_B + NSTG * STAGE_B_BYTES)  // 55296
#define SM_SQB (SM_SQA + 512)
#define SM_LABA (SM_SQB + 256)
#define SM_LABB (SM_LABA + 512)
#define SM_RED (SM_LABB + 256)
#define SMEM_TOTAL (SM_RED + 128)             // 56960

__device__ float g_sq[MAXN];
__device__ __align__(16) uint8_t g_Xf8[MAXN * MAXD];
__device__ double g_sum1;
__device__ double g_sum2;
__device__ unsigned long long g_cnt;
__device__ unsigned int g_done;

__device__ __forceinline__ uint32_t smem_u32(const void* p) {
    uint32_t a;
    asm("{ .reg .u64 t; cvta.to.shared.u64 t, %1; cvt.u32.u64 %0, t; }"
        : "=r"(a) : "l"(p));
    return a;
}

#define CP_ASYNC16(dst_u32, src) \
    asm volatile("cp.async.cg.shared.global [%0], [%1], 16;" :: "r"(dst_u32), "l"(src))
#define CP_COMMIT() asm volatile("cp.async.commit_group;" ::: "memory")
#define CP_WAIT0()  asm volatile("cp.async.wait_group 0;" ::: "memory")

// LDSM stays volatile: it must not move above the __syncthreads that
// publishes the cp.async data.
#define LDSM_X4(r0, r1, r2, r3, a)                                        \
    asm volatile("ldmatrix.sync.aligned.m8n8.x4.shared.b16 "              \
                 "{%0,%1,%2,%3}, [%4];"                                   \
                 : "=r"(r0), "=r"(r1), "=r"(r2), "=r"(r3) : "r"(a))

// MMA is NON-volatile: pure register math; data deps protect correctness and
// the scheduler may interleave it freely with LDSMs.
#define MMA16832(c, a0, a1, a2, a3, b0, b1)                               \
    asm("mma.sync.aligned.m16n8k32.row.col.f32.e4m3.e4m3.f32 "            \
        "{%0,%1,%2,%3}, {%4,%5,%6,%7}, {%8,%9}, {%0,%1,%2,%3};"           \
        : "+f"((c)[0]), "+f"((c)[1]), "+f"((c)[2]), "+f"((c)[3])          \
        : "r"(a0), "r"(a1), "r"(a2), "r"(a3), "r"(b0), "r"(b1))

__device__ __forceinline__ uint32_t pack_e4m3x4(float4 v) {
    uint16_t lo, hi;
    asm("cvt.rn.satfinite.e4m3x2.f32 %0, %1, %2;" : "=h"(lo) : "f"(v.y), "f"(v.x));
    asm("cvt.rn.satfinite.e4m3x2.f32 %0, %1, %2;" : "=h"(hi) : "f"(v.w), "f"(v.z));
    return (uint32_t)lo | ((uint32_t)hi << 16);
}

// Blocks (br, bc) with bc in [2*br, ntn): rl starts at ntn, shrinks by 2.
__device__ __forceinline__ void decode_tile(int t, int ntn, int& br, int& bc) {
    int b = t, r = 0, rl = ntn;
    while (b >= rl) {
        b -= rl;
        rl -= 2;
        r++;
    }
    br = r;
    bc = 2 * r + b;
}

// ---------------------------------------------------------------------------
// Kernel A: X -> e4m3 + exact fp32 row norms. One warp per row.
// ---------------------------------------------------------------------------
__global__ void __launch_bounds__(128) convert_kernel(const float* __restrict__ X,
                                                      int n, int d) {
    if (blockIdx.x == 0 && threadIdx.x == 0) {
        g_sum1 = 0.0;
        g_sum2 = 0.0;
        g_cnt = 0ull;
        g_done = 0u;
    }
    const int w = threadIdx.x >> 5, l = threadIdx.x & 31;
    const int row = blockIdx.x * 4 + w;
    if (row >= n) return;
    const float4* src = reinterpret_cast<const float4*>(X + (size_t)row * d);
    uint32_t* dst = reinterpret_cast<uint32_t*>(g_Xf8 + (size_t)row * d);
    float s = 0.0f;
    if (d == 512) {
        float4 v[4];
#pragma unroll
        for (int i = 0; i < 4; i++) v[i] = src[l + 32 * i];
#pragma unroll
        for (int i = 0; i < 4; i++) {
            s = fmaf(v[i].x, v[i].x,
                     fmaf(v[i].y, v[i].y,
                          fmaf(v[i].z, v[i].z, fmaf(v[i].w, v[i].w, s))));
            dst[l + 32 * i] = pack_e4m3x4(v[i]);
        }
    } else {
        for (int c4 = l; c4 * 4 < d; c4 += 32) {
            float4 v = src[c4];
            s = fmaf(v.x, v.x, fmaf(v.y, v.y, fmaf(v.z, v.z, fmaf(v.w, v.w, s))));
            dst[c4] = pack_e4m3x4(v);
        }
    }
#pragma unroll
    for (int o = 16; o > 0; o >>= 1) s += __shfl_down_sync(0xffffffffu, s, o);
    if (l == 0) g_sq[row] = s;
}

// ---------------------------------------------------------------------------
// Kernel B: persistent fp8 Gram (128x64 blocks) + fused epilogue + finalize.
// ---------------------------------------------------------------------------
__global__ void __launch_bounds__(NTHREADS, 3) pair_kernel(
    const int* __restrict__ lab, const float* __restrict__ marginp,
    float* __restrict__ out, int n, int d, int ntn, int nb) {
    extern __shared__ __align__(1024) uint8_t smem[];
    const uint32_t sbase = smem_u32(smem);
    float* sqA = reinterpret_cast<float*>(smem + SM_SQA);
    float* sqB = reinterpret_cast<float*>(smem + SM_SQB);
    int* labA = reinterpret_cast<int*>(smem + SM_LABA);
    int* labB = reinterpret_cast<int*>(smem + SM_LABB);

    const int tid = threadIdx.x;
    const int wid = tid >> 5, lane = tid & 31;
    const int warpM = wid & 3;   // 4 warps over M: 32 rows each
    const int warpN = wid >> 2;  // 2 warps over N: 32 cols each

    const int nChunks = d / BK;  // 4 for d=512
    const int stride = gridDim.x;
    int myTiles = 0;
    for (int t = blockIdx.x; t < nb; t += stride) myTiles++;
    const int total = myTiles * nChunks;

    const uint8_t* __restrict__ Xb = g_Xf8;
    const float margin = *marginp;

    const int ldRow = tid >> 3;
    const int ldKC = (tid & 7) * 16;
    const uint32_t sOffBase = (uint32_t)ldRow * SSTRB + (uint32_t)ldKC;
    uint32_t gAbase = 0, gBbase = 0;

    float acc[2][4][4];  // [mt][ntile][e]
#pragma unroll
    for (int mt = 0; mt < 2; mt++)
#pragma unroll
        for (int ntile = 0; ntile < 4; ntile++)
#pragma unroll
            for (int e = 0; e < 4; e++) acc[mt][ntile][e] = 0.0f;

    const uint32_t laneRow = (uint32_t)(lane & 15) * SSTRB;
    const uint32_t laneK = (uint32_t)(lane >> 4) * 16;
    const uint32_t aLane = (uint32_t)(warpM * 32) * SSTRB + laneRow + laneK;
    const uint32_t bLane = (uint32_t)(warpN * 32) * SSTRB + laneRow + laneK;

    float s1 = 0.0f, s2 = 0.0f;
    unsigned int cnt = 0;

    int cpK = 0, cpRB = 0, cpCB = 0;
    int ldK = 0;
    if (myTiles > 0) {
        decode_tile(blockIdx.x, ntn, cpRB, cpCB);
        gAbase = (uint32_t)(cpRB * BM + ldRow) * (uint32_t)d + (uint32_t)ldKC;
        gBbase = (uint32_t)(cpCB * BN + ldRow) * (uint32_t)d + (uint32_t)ldKC;
    }

    // Straightline chunk loader (A: 128 rows in 4 slabs, B: 64 rows in 2).
#define LOAD_CHUNK(cc, slot)                                                   \
    do {                                                                       \
        const uint32_t aB_ = sbase + SM_A + (uint32_t)(slot) * STAGE_A_BYTES;  \
        const uint32_t bB_ = sbase + SM_B + (uint32_t)(slot) * STAGE_B_BYTES;  \
        const uint32_t ck_ = (uint32_t)((cc) * BK);                            \
        CP_ASYNC16(aB_ + sOffBase + 0u * (32 * SSTRB),                         \
                   Xb + gAbase + ck_ + 0u * 32u * (uint32_t)d);                \
        CP_ASYNC16(aB_ + sOffBase + 1u * (32 * SSTRB),                         \
                   Xb + gAbase + ck_ + 1u * 32u * (uint32_t)d);                \
        CP_ASYNC16(aB_ + sOffBase + 2u * (32 * SSTRB),                         \
                   Xb + gAbase + ck_ + 2u * 32u * (uint32_t)d);                \
        CP_ASYNC16(aB_ + sOffBase + 3u * (32 * SSTRB),                         \
                   Xb + gAbase + ck_ + 3u * 32u * (uint32_t)d);                \
        CP_ASYNC16(bB_ + sOffBase + 0u * (32 * SSTRB),                         \
                   Xb + gBbase + ck_ + 0u * 32u * (uint32_t)d);                \
        CP_ASYNC16(bB_ + sOffBase + 1u * (32 * SSTRB),                         \
                   Xb + gBbase + ck_ + 1u * 32u * (uint32_t)d);                \
    } while (0)

    if (total > 0) LOAD_CHUNK(0, 0);
    CP_COMMIT();

    for (int gs = 0; gs < total; gs++) {
        const int c = gs & (nChunks - 1);
        CP_WAIT0();
        __syncthreads();

        if (c == 0) {
            if (tid < 128) {
                sqA[tid] = g_sq[cpRB * BM + tid];
                labA[tid] = lab[cpRB * BM + tid];
            } else if (tid < 192) {
                int i = tid - 128;
                sqB[i] = g_sq[cpCB * BN + i];
                labB[i] = lab[cpCB * BN + i];
            }
        }

        const int gl = gs + 1;
        if (gl < total) {
            const int lk = gl / nChunks;
            if (lk != ldK) {
                ldK = lk;
                int rb, cb;
                decode_tile(blockIdx.x + lk * stride, ntn, rb, cb);
                gAbase = (uint32_t)(rb * BM + ldRow) * (uint32_t)d + (uint32_t)ldKC;
                gBbase = (uint32_t)(cb * BN + ldRow) * (uint32_t)d + (uint32_t)ldKC;
            }
            LOAD_CHUNK(gl & (nChunks - 1), gl & (NSTG - 1));
        }
        CP_COMMIT();

        const uint32_t slot = (uint32_t)(gs & (NSTG - 1));
        const uint32_t aBase = sbase + SM_A + slot * STAGE_A_BYTES + aLane;
        const uint32_t bBase = sbase + SM_B + slot * STAGE_B_BYTES + bLane;

        // BK=128 -> 4 k32-steps; MMAs are non-volatile so ptxas interleaves
        // them with the (volatile) LDSMs of subsequent steps.
#pragma unroll
        for (int ks = 0; ks < 4; ks++) {
            uint32_t a[2][4];
#pragma unroll
            for (int mt = 0; mt < 2; mt++)
                LDSM_X4(a[mt][0], a[mt][1], a[mt][2], a[mt][3],
                        aBase + (uint32_t)mt * 16 * SSTRB + (uint32_t)ks * 32);
#pragma unroll
            for (int ntp = 0; ntp < 2; ntp++) {
                uint32_t r0, r1, r2, r3;
                LDSM_X4(r0, r1, r2, r3,
                        bBase + (uint32_t)ntp * 16 * SSTRB + (uint32_t)ks * 32);
#pragma unroll
                for (int mt = 0; mt < 2; mt++) {
                    MMA16832(acc[mt][2 * ntp + 0], a[mt][0], a[mt][1], a[mt][2],
                             a[mt][3], r0, r2);
                    MMA16832(acc[mt][2 * ntp + 1], a[mt][0], a[mt][1], a[mt][2],
                             a[mt][3], r1, r3);
                }
            }
        }

        if (c == nChunks - 1) {
            const int rowBase = cpRB * BM, colBase = cpCB * BN;
            const bool straddle = (cpCB - 2 * cpRB) < 2;
#pragma unroll
            for (int mt = 0; mt < 2; mt++) {
                const int i0 = warpM * 32 + mt * 16 + (lane >> 2);
#pragma unroll
                for (int half = 0; half < 2; half++) {
                    const int iloc = i0 + half * 8;
                    const int gi = rowBase + iloc;
                    const float sqi = sqA[iloc];
                    const int li = labA[iloc];
#pragma unroll
                    for (int ntile = 0; ntile < 4; ntile++) {
#pragma unroll
                        for (int e = 0; e < 2; e++) {
                            const int jloc =
                                warpN * 32 + ntile * 8 + (lane & 3) * 2 + e;
                            const int gj = colBase + jloc;
                            float w = 2.0f;
                            if (straddle)
                                w = (gi > gj) ? 0.0f : ((gi == gj) ? 1.0f : 2.0f);
                            if (w != 0.0f) {
                                float D = sqi + sqB[jloc] -
                                          2.0f * acc[mt][ntile][half * 2 + e];
                                D = fmaxf(D, 0.0f);
                                if (li == labB[jloc]) {
                                    s1 += w * D;
                                    cnt += (unsigned int)w;
                                } else {
                                    s2 += w * fmaxf(0.0f, margin - D);
                                }
                            }
                            acc[mt][ntile][half * 2 + e] = 0.0f;
                        }
                    }
                }
            }
            cpK++;
            if (cpK < myTiles)
                decode_tile(blockIdx.x + cpK * stride, ntn, cpRB, cpCB);
        }
    }

    // One block reduction + atomics per CTA.
#pragma unroll
    for (int o = 16; o > 0; o >>= 1) {
        s1 += __shfl_down_sync(0xffffffffu, s1, o);
        s2 += __shfl_down_sync(0xffffffffu, s2, o);
        cnt += __shfl_down_sync(0xffffffffu, cnt, o);
    }
    float* r1 = reinterpret_cast<float*>(smem + SM_RED);
    float* r2 = r1 + 8;
    unsigned int* rc = reinterpret_cast<unsigned int*>(r2 + 8);
    __syncthreads();
    if (lane == 0) {
        r1[wid] = s1;
        r2[wid] = s2;
        rc[wid] = cnt;
    }
    __syncthreads();
    if (tid == 0) {
        double t1 = 0.0, t2 = 0.0;
        unsigned int tc = 0;
#pragma unroll
        for (int w = 0; w < 8; w++) {
            t1 += (double)r1[w];
            t2 += (double)r2[w];
            tc += rc[w];
        }
        atomicAdd(&g_sum1, t1);
        atomicAdd(&g_sum2, t2);
        atomicAdd(&g_cnt, (unsigned long long)tc);

        __threadfence();
        unsigned int old = atomicAdd(&g_done, 1u);
        if (old == gridDim.x - 1) {
            double zn1 = (double)atomicAdd(&g_cnt, 0ull);
            double t1f = atomicAdd(&g_sum1, 0.0);
            double t2f = atomicAdd(&g_sum2, 0.0);
            double zn2 = (double)n * (double)n - zn1;
            out[0] = (float)(0.5 * (t1f / zn1 + t2f / zn2));
            g_done = 0u;
        }
    }
}

extern "C" void kernel_launch(void* const* d_in, const int* in_sizes, int n_in,
                              void* d_out, int out_size) {
    const float* X = (const float*)d_in[0];
    const int* lab = (const int*)d_in[1];
    const float* marginp = (const float*)d_in[2];
    float* out = (float*)d_out;

    int n = in_sizes[1];
    int d = in_sizes[0] / n;

    cudaFuncSetAttribute(pair_kernel,
                         cudaFuncAttributeMaxDynamicSharedMemorySize, SMEM_TOTAL);

    convert_kernel<<<(n + 3) / 4, 128>>>(X, n, d);

    int ntm = n / BM;                       // 32
    int ntn = n / BN;                       // 64
    int nb = ntm * ntn - ntm * (ntm - 1);   // 1056 blocks of 128x64
    int ctas = nb < 444 ? nb : 444;         // 3 persistent CTAs per SM
    pair_kernel<<<ctas, NTHREADS, SMEM_TOTAL>>>(lab, marginp, out, n, d, ntn, nb);
}